// round 7
// baseline (speedup 1.0000x reference)
#include <cuda_runtime.h>

// Problem constants (fixed by setup_inputs): B=4, N=M=8192, D=3
constexpr int Bn = 4;
constexpr int Nn = 8192;
constexpr int Mn = 8192;
constexpr int BN = Bn * Nn;  // 32768 (= Bn*Mn too)

constexpr int TC    = 256;   // target chunk staged in shared
constexpr int R     = 8;     // source rows per thread
constexpr int T     = 128;   // threads per block
constexpr int ST    = T * R; // 1024 source rows per block
constexpr int NWARP = T / 32;
constexpr int NBX   = Mn / TC;  // 32 target chunks
constexpr int NBY   = Nn / ST;  // 8 source tiles

// Partial-min scratch (written unconditionally every call -> no init needed)
__device__ float g_rowp[NBX * BN];   // [bx][b*Nn+row] : row min of d2 over chunk bx
__device__ float g_colp[NBY * BN];   // [by][b*Mn+col] : col min of d2 over tile by
__device__ float g_bsum[256];        // per-block partial sums from reduce stage

// FFMA with immediate multiplier 1.0 -> rt=1 imm-form, not demotable to FADD
__device__ __forceinline__ float fma1(float a, float c) {
    float d; asm("fma.rn.f32 %0, %1, 0f3F800000, %2;" : "=f"(d) : "f"(a), "f"(c));
    return d;
}
// Bare warp min-reduce (REDUX), no extra sync envelope
__device__ __forceinline__ unsigned redux_min(unsigned v) {
    unsigned d;
    asm("redux.sync.min.u32 %0, %1, 0xffffffff;" : "=r"(d) : "r"(v));
    return d;
}

__global__ __launch_bounds__(T, 7)   // 7*148 >= 1024 blocks: one wave
void chamfer_main(const float* __restrict__ src, const float* __restrict__ tgt) {
    __shared__ float4   tsh[TC];          // target x,y,z,|t|^2
    __shared__ unsigned scolw[NWARP][TC]; // per-warp column min (raw bits, nonneg)

    const int tid  = threadIdx.x;
    const int w    = tid >> 5;
    const int bx   = blockIdx.x;
    const int by   = blockIdx.y;
    const int b    = blockIdx.z;
    const int s0   = by * ST;
    const int t0   = bx * TC;

    // Stage target chunk into shared (x, y, z, |t|^2)
    for (int i = tid; i < TC; i += T) {
        const float* p = tgt + ((size_t)b * Mn + t0 + i) * 3;
        float x = p[0], y = p[1], z = p[2];
        tsh[i] = make_float4(x, y, z, fmaf(x, x, fmaf(y, y, z * z)));
    }

    // Source rows: NEGATED-DOUBLED coords so the dot chain seeds with t.w
    float sxn[R], syn[R], szn[R], sqs[R], flmin[R];
    const float INF = __int_as_float(0x7f800000);
#pragma unroll
    for (int r = 0; r < R; r++) {
        int row = s0 + tid + r * T;
        const float* p = src + ((size_t)b * Nn + row) * 3;
        float x = p[0], y = p[1], z = p[2];
        sxn[r] = -2.0f * x; syn[r] = -2.0f * y; szn[r] = -2.0f * z;
        sqs[r] = fmaf(x, x, fmaf(y, y, z * z));
        flmin[r] = INF;   // min over j of d2 -> row partial, directly
    }
    __syncthreads();

    // Main sweep. No branches in the body: the column result is stored
    // unconditionally by ALL lanes (same value, same address -> one write,
    // no BSSY/BSYNC convergence barrier).
#pragma unroll 16
    for (int j = 0; j < TC; j++) {
        float4 t = tsh[j];  // broadcast LDS.128, conflict-free
        float fl[R];
#pragma unroll
        for (int r = 0; r < R; r++) {
            float e = fmaf(sxn[r], t.x, t.w);   // FFMA
            e = fmaf(syn[r], t.y, e);           // FFMA
            e = fmaf(szn[r], t.z, e);           // FFMA   e = |t|^2 - 2c
            fl[r] = fma1(e, sqs[r]);            // FFMA-imm: d2 = e + |s|^2
            flmin[r] = fminf(flmin[r], fl[r]);  // row-min of d2
        }
        // Tree-min over this thread's 8 rows -> column candidate
#pragma unroll
        for (int s = R / 2; s > 0; s >>= 1)
#pragma unroll
            for (int r = 0; r < s; r++) fl[r] = fminf(fl[r], fl[r + s]);
        // Clamp tiny negative rounding artifacts -> raw bits order-preserving
        unsigned k = redux_min(__float_as_uint(fmaxf(fl[0], 0.0f)));
        scolw[w][j] = k;   // all lanes, same value, same address: branch-free
    }
    __syncthreads();

    // Column partials: min of d2 over this block's 1024 rows
    for (int j = tid; j < TC; j += T) {
        unsigned m = min(min(scolw[0][j], scolw[1][j]),
                         min(scolw[2][j], scolw[3][j]));
        g_colp[by * BN + b * Mn + t0 + j] = __uint_as_float(m);
    }
    // Row partials: flmin IS the row d2 min for this chunk (coalesced)
#pragma unroll
    for (int r = 0; r < R; r++)
        g_rowp[bx * BN + b * Nn + s0 + tid + r * T] = flmin[r];
}

// Stage 2: blocks 0..127 reduce rows, 128..255 reduce cols. Fixed-order sums.
__global__ void reduce_partials() {
    __shared__ float sh[256];
    const int tid = threadIdx.x;
    const int blk = blockIdx.x;
    float s;
    if (blk < 128) {
        int gr = blk * 256 + tid;  // one row per thread (128*256 = 32768)
        float m = g_rowp[gr];
#pragma unroll
        for (int k = 1; k < NBX; k++) m = fminf(m, g_rowp[k * BN + gr]);
        s = m;
    } else {
        int gc = (blk - 128) * 256 + tid;
        float m = g_colp[gc];
#pragma unroll
        for (int k = 1; k < NBY; k++) m = fminf(m, g_colp[k * BN + gc]);
        s = m;
    }
    sh[tid] = s;
    __syncthreads();
#pragma unroll
    for (int st = 128; st > 0; st >>= 1) {
        if (tid < st) sh[tid] += sh[tid + st];
        __syncthreads();
    }
    if (tid == 0) g_bsum[blk] = sh[0];
}

__global__ void final_sum(float* out) {
    __shared__ float sh[256];
    int tid = threadIdx.x;
    sh[tid] = g_bsum[tid];
    __syncthreads();
#pragma unroll
    for (int st = 128; st > 0; st >>= 1) {
        if (tid < st) sh[tid] += sh[tid + st];
        __syncthreads();
    }
    if (tid == 0)
        out[0] = sh[0] / (float)(Bn * Nn);  // (sum_rows + sum_cols) / (B*G)
}

extern "C" void kernel_launch(void* const* d_in, const int* in_sizes, int n_in,
                              void* d_out, int out_size) {
    const float* src = (const float*)d_in[0];  // (4, 8192, 3) fp32
    const float* tgt = (const float*)d_in[1];  // (4, 8192, 3) fp32
    float* out = (float*)d_out;

    dim3 grid(NBX, NBY, Bn);  // (32, 8, 4) = 1024 blocks
    chamfer_main<<<grid, T>>>(src, tgt);
    reduce_partials<<<256, 256>>>();
    final_sum<<<1, 256>>>(out);
}

// round 8
// speedup vs baseline: 1.0324x; 1.0324x over previous
#include <cuda_runtime.h>

// Problem constants (fixed by setup_inputs): B=4, N=M=8192, D=3
constexpr int Bn = 4;
constexpr int Nn = 8192;
constexpr int Mn = 8192;
constexpr int BN = Bn * Nn;  // 32768 (= Bn*Mn too)

constexpr int TC    = 256;   // target chunk staged in shared
constexpr int R     = 8;     // source rows per thread
constexpr int T     = 128;   // threads per block
constexpr int ST    = T * R; // 1024 source rows per block
constexpr int NWARP = T / 32;
constexpr int NBX   = Mn / TC;  // 32 target chunks
constexpr int NBY   = Nn / ST;  // 8 source tiles
constexpr int NCS   = NBY * NWARP;  // 32 column-partial slices (per-warp)

// Partial-min scratch (written unconditionally every call -> no init needed)
__device__ float g_rowp[NBX * BN];   // [bx][b*Nn+row] : row min of d2 over chunk bx
__device__ float g_colp[NCS * BN];   // [by*4+w][b*Mn+col] : per-warp col min of d2
__device__ float g_bsum[256];        // per-block partial sums from reduce stage

// FFMA with immediate multiplier 1.0 -> rt=1 imm-form, not demotable to FADD
__device__ __forceinline__ float fma1(float a, float c) {
    float d; asm("fma.rn.f32 %0, %1, 0f3F800000, %2;" : "=f"(d) : "f"(a), "f"(c));
    return d;
}
// Bare warp min-reduce (REDUX)
__device__ __forceinline__ unsigned redux_min(unsigned v) {
    unsigned d;
    asm("redux.sync.min.u32 %0, %1, 0xffffffff;" : "=r"(d) : "r"(v));
    return d;
}

__global__ __launch_bounds__(T, 7)   // 7*148 >= 1024 blocks: one wave
void chamfer_main(const float* __restrict__ src, const float* __restrict__ tgt) {
    __shared__ float4 tsh[TC];   // target x,y,z,|t|^2  (only smem use: 4KB)

    const int tid  = threadIdx.x;
    const int lane = tid & 31;
    const int w    = tid >> 5;
    const int bx   = blockIdx.x;
    const int by   = blockIdx.y;
    const int b    = blockIdx.z;
    const int s0   = by * ST;
    const int t0   = bx * TC;

    // Stage target chunk into shared (x, y, z, |t|^2)
    for (int i = tid; i < TC; i += T) {
        const float* p = tgt + ((size_t)b * Mn + t0 + i) * 3;
        float x = p[0], y = p[1], z = p[2];
        tsh[i] = make_float4(x, y, z, fmaf(x, x, fmaf(y, y, z * z)));
    }

    // Source rows: NEGATED-DOUBLED coords so the dot chain seeds with t.w
    float sxn[R], syn[R], szn[R], sqs[R], flmin[R];
    const float INF = __int_as_float(0x7f800000);
#pragma unroll
    for (int r = 0; r < R; r++) {
        int row = s0 + tid + r * T;
        const float* p = src + ((size_t)b * Nn + row) * 3;
        float x = p[0], y = p[1], z = p[2];
        sxn[r] = -2.0f * x; syn[r] = -2.0f * y; szn[r] = -2.0f * z;
        sqs[r] = fmaf(x, x, fmaf(y, y, z * z));
        flmin[r] = INF;   // min over j of d2 -> row partial, directly
    }
    __syncthreads();

    // Column-partial output slice for this warp
    float* colp = g_colp + ((size_t)(by * NWARP + w)) * BN + b * Mn + t0;

    // Main sweep in groups of 32 columns. MIO ops per j: LDS + REDUX only.
    // The per-column result is captured into a register by lane j%32 (ALU SEL),
    // and flushed once per group as a coalesced STG.
#pragma unroll 1
    for (int g = 0; g < TC / 32; g++) {
        unsigned cg = 0x7f800000u;  // +INF bits
#pragma unroll
        for (int jc = 0; jc < 32; jc++) {
            float4 t = tsh[g * 32 + jc];  // broadcast LDS.128
            float fl[R];
#pragma unroll
            for (int r = 0; r < R; r++) {
                float e = fmaf(sxn[r], t.x, t.w);   // FFMA
                e = fmaf(syn[r], t.y, e);           // FFMA
                e = fmaf(szn[r], t.z, e);           // FFMA   e = |t|^2 - 2c
                fl[r] = fma1(e, sqs[r]);            // FFMA-imm: d2 = e + |s|^2
                flmin[r] = fminf(flmin[r], fl[r]);  // row-min of d2
            }
            // Tree-min over this thread's 8 rows -> warp column candidate
#pragma unroll
            for (int s = R / 2; s > 0; s >>= 1)
#pragma unroll
                for (int r = 0; r < s; r++) fl[r] = fminf(fl[r], fl[r + s]);
            // Clamp tiny negative rounding artifacts -> raw bits order-preserving
            unsigned k = redux_min(__float_as_uint(fmaxf(fl[0], 0.0f)));
            cg = (lane == jc) ? k : cg;  // ALU capture, no smem
        }
        colp[g * 32 + lane] = __uint_as_float(cg);  // coalesced per-warp STG
    }

    // Row partials: flmin IS the row d2 min for this chunk (coalesced)
#pragma unroll
    for (int r = 0; r < R; r++)
        g_rowp[bx * BN + b * Nn + s0 + tid + r * T] = flmin[r];
}

// Stage 2: blocks 0..127 reduce rows, 128..255 reduce cols (32 slices each).
__global__ void reduce_partials() {
    __shared__ float sh[256];
    const int tid = threadIdx.x;
    const int blk = blockIdx.x;
    const float* base = (blk < 128) ? g_rowp : g_colp;
    const int gi = (blk & 127) * 256 + tid;  // one row/col per thread
    float m = base[gi];
#pragma unroll
    for (int k = 1; k < 32; k++) m = fminf(m, base[k * BN + gi]);
    sh[tid] = m;
    __syncthreads();
#pragma unroll
    for (int st = 128; st > 0; st >>= 1) {
        if (tid < st) sh[tid] += sh[tid + st];
        __syncthreads();
    }
    if (tid == 0) g_bsum[blk] = sh[0];
}

__global__ void final_sum(float* out) {
    __shared__ float sh[256];
    int tid = threadIdx.x;
    sh[tid] = g_bsum[tid];
    __syncthreads();
#pragma unroll
    for (int st = 128; st > 0; st >>= 1) {
        if (tid < st) sh[tid] += sh[tid + st];
        __syncthreads();
    }
    if (tid == 0)
        out[0] = sh[0] / (float)(Bn * Nn);  // (sum_rows + sum_cols) / (B*G)
}

extern "C" void kernel_launch(void* const* d_in, const int* in_sizes, int n_in,
                              void* d_out, int out_size) {
    const float* src = (const float*)d_in[0];  // (4, 8192, 3) fp32
    const float* tgt = (const float*)d_in[1];  // (4, 8192, 3) fp32
    float* out = (float*)d_out;

    dim3 grid(NBX, NBY, Bn);  // (32, 8, 4) = 1024 blocks
    chamfer_main<<<grid, T>>>(src, tgt);
    reduce_partials<<<256, 256>>>();
    final_sum<<<1, 256>>>(out);
}